// round 15
// baseline (speedup 1.0000x reference)
#include <cuda_runtime.h>
#include <cuda_fp16.h>
#include <math.h>

#define HW       2304      // 48*48
#define NPIX     9216      // 96*96
#define XT_SLAB  294912    // 48*48*128
#define K_SLAB   73728     // 48*48*32

__device__ __align__(128) float  g_xt [4*XT_SLAB];  // x channel-last per (b,g) fp32
__device__ __align__(128) __half g_xh [4*XT_SLAB];  // fp16 shadow of v for k6 gather
__device__ __align__(128) __half g_kh [4*K_SLAB];   // k channel-last per (b,g), fp16
__device__ __align__(128) float  g_q  [4*K_SLAB];   // q lowres channel-last
__device__ __align__(128) float  g_t  [4*NPIX*32];  // gelu(ln(dwconv(resize(q))))
__device__ __align__(128) float  g_crd[4*NPIX*18];  // (iy,ix) per (bg,pix,tap)
__device__ float g_mu[2*HW], g_rstd[2*HW];
__device__ __align__(128) float g_WT[256*128];      // [c][o]; o<64: Wq, o>=64: Wk (LN-gain folded)
__device__ float g_csum[128], g_bias2[128];
__device__ __align__(128) float g_w2[2*9*9*32];     // [half][k][j][c]

// ---------------- k01: fused prep (blocks 0-148) + transpose/LN (blocks 149-244)
__global__ void k01_prep_tr(const float* __restrict__ Wq, const float* __restrict__ Wk,
                            const float* __restrict__ g, const float* __restrict__ b,
                            const float* __restrict__ off_w, const float* __restrict__ x)
{
    __shared__ float xs[128*49];
    __shared__ float ssum[48], ssq[48];
    int t = threadIdx.x; // 256
    if (blockIdx.x < 128) {
        int o = blockIdx.x, c = t;
        const float* Wr = (o < 64) ? (Wq + o*256) : (Wk + (o-64)*256);
        float w  = Wr[c];
        float gc = g[c];
        g_WT[c*128 + o] = w*gc;
        float cs = w*gc, bs = w*b[c];
        #pragma unroll
        for (int off = 16; off; off >>= 1) {
            cs += __shfl_xor_sync(0xffffffffu, cs, off);
            bs += __shfl_xor_sync(0xffffffffu, bs, off);
        }
        int wid = c >> 5, lane = c & 31;
        if (lane == 0) { xs[wid] = cs; xs[16 + wid] = bs; }
        __syncthreads();
        if (c == 0) {
            float a = 0.f, bbv = 0.f;
            #pragma unroll
            for (int i = 0; i < 8; i++) { a += xs[i]; bbv += xs[16 + i]; }
            g_csum[o] = a; g_bias2[o] = bbv;
        }
        return;
    }
    if (blockIdx.x < 149) {
        int i = (blockIdx.x - 128)*256 + t;
        if (i < 2*9*9*32) {
            int c = i & 31; int j = (i >> 5) % 9; int k = (i/288) % 9; int half = i/2592;
            g_w2[i] = off_w[((j*2+half)*32 + c)*9 + k];
        }
        return;
    }
    int bid = blockIdx.x - 149;          // 0..95
    int b2 = bid / 48, y = bid % 48;
    if (t < 48) { ssum[t] = 0.f; ssq[t] = 0.f; }
    int wid = t >> 5, lane = t & 31;
    for (int half = 0; half < 2; half++) {
        __syncthreads();
        const float* src = x + ((size_t)(b2*256 + half*128))*HW + y*48;
        for (int idx = t; idx < 128*48; idx += 256) {
            int c = idx / 48, xx = idx - c*48;
            xs[c*49 + xx] = src[(size_t)c*HW + xx];
        }
        __syncthreads();
        for (int xx = wid; xx < 48; xx += 8) {
            float s = 0.f, q = 0.f;
            #pragma unroll
            for (int j = 0; j < 4; j++) { float v = xs[(lane + 32*j)*49 + xx]; s += v; q += v*v; }
            #pragma unroll
            for (int o = 16; o; o >>= 1) { s += __shfl_xor_sync(0xffffffffu, s, o); q += __shfl_xor_sync(0xffffffffu, q, o); }
            if (lane == 0) { ssum[xx] += s; ssq[xx] += q; }
        }
        size_t base = ((size_t)(b2*2 + half))*XT_SLAB + (size_t)y*48*128;
        float*  dst = g_xt + base;
        __half* dsh = g_xh + base;
        for (int idx = t; idx < 128*48; idx += 256) {
            int xx = idx >> 7, c = idx & 127;
            float v = xs[c*49 + xx];
            dst[xx*128 + c] = v;
            dsh[xx*128 + c] = __float2half_rn(v);
        }
    }
    __syncthreads();
    if (t < 48) {
        float mu = ssum[t] * (1.0f/256.0f);
        float var = ssq[t] * (1.0f/256.0f) - mu*mu;
        int p = b2*HW + y*48 + t;
        g_mu[p] = mu;
        g_rstd[p] = rsqrtf(var + 1e-5f);
    }
}

// ---------------- k2: Q/K projection (2px x 8out per thread) ------------------
__global__ void k2_qk()
{
    int t = threadIdx.x;                 // 256
    int og = t & 15, pg = t >> 4;        // 16 px-groups x 2 px
    int P0 = blockIdx.x*32 + pg*2;       // 0..4606
    int b = P0 / HW, p0 = P0 % HW;
    int o0 = og*8;
    const float* xA = g_xt + (size_t)(b*2)*XT_SLAB + (size_t)p0*128;
    float accA[8], accB[8];
    #pragma unroll
    for (int j = 0; j < 8; j++) { accA[j] = 0.f; accB[j] = 0.f; }

    for (int h2 = 0; h2 < 2; h2++) {
        const float4* xpA = (const float4*)(xA + (size_t)h2*XT_SLAB);
        const float4* xpB = xpA + 32;
        #pragma unroll 4
        for (int c4 = 0; c4 < 32; c4++) {
            float4 xa = xpA[c4];
            float4 xb = xpB[c4];
            const float* wb = &g_WT[(h2*128 + c4*4)*128 + o0];
            #pragma unroll
            for (int cc = 0; cc < 4; cc++) {
                float4 w0 = *(const float4*)&wb[cc*128];
                float4 w1 = *(const float4*)&wb[cc*128 + 4];
                float va = (cc == 0) ? xa.x : (cc == 1) ? xa.y : (cc == 2) ? xa.z : xa.w;
                float vb = (cc == 0) ? xb.x : (cc == 1) ? xb.y : (cc == 2) ? xb.z : xb.w;
                accA[0] += va*w0.x; accA[1] += va*w0.y; accA[2] += va*w0.z; accA[3] += va*w0.w;
                accA[4] += va*w1.x; accA[5] += va*w1.y; accA[6] += va*w1.z; accA[7] += va*w1.w;
                accB[0] += vb*w0.x; accB[1] += vb*w0.y; accB[2] += vb*w0.z; accB[3] += vb*w0.w;
                accB[4] += vb*w1.x; accB[5] += vb*w1.y; accB[6] += vb*w1.z; accB[7] += vb*w1.w;
            }
        }
    }
    int isK = (o0 >= 64);
    int oo  = o0 & 63;
    int grp = oo >> 5, cl0 = oo & 31;
    #pragma unroll
    for (int px = 0; px < 2; px++) {
        float* acc = px ? accB : accA;
        int p = p0 + px;
        float mu = g_mu[b*HW + p], rs = g_rstd[b*HW + p];
        float vv[8];
        #pragma unroll
        for (int j = 0; j < 8; j++)
            vv[j] = rs*(acc[j] - mu*g_csum[o0+j]) + g_bias2[o0+j];
        if (isK) {
            __half* dsth = g_kh + (size_t)(b*2 + grp)*K_SLAB + (size_t)p*32 + cl0;
            __half2 h0 = __floats2half2_rn(vv[0], vv[1]);
            __half2 h1 = __floats2half2_rn(vv[2], vv[3]);
            __half2 h2 = __floats2half2_rn(vv[4], vv[5]);
            __half2 h3 = __floats2half2_rn(vv[6], vv[7]);
            uint4 pk;
            pk.x = *(unsigned*)&h0; pk.y = *(unsigned*)&h1;
            pk.z = *(unsigned*)&h2; pk.w = *(unsigned*)&h3;
            *(uint4*)dsth = pk;
        } else {
            float* dst = g_q + (size_t)(b*2 + grp)*K_SLAB + (size_t)p*32 + cl0;
            *(float4*)&dst[0] = make_float4(vv[0], vv[1], vv[2], vv[3]);
            *(float4*)&dst[4] = make_float4(vv[4], vv[5], vv[6], vv[7]);
        }
    }
}

// ---------------- k4: inline resize + depthwise 3x3 + channel-LN + GeLU -------
__global__ void k4_dw(const float* __restrict__ dw_w,
                      const float* __restrict__ offg, const float* __restrict__ offb)
{
    __shared__ float sq[32*108];         // 13.8 KB, [c][ky(3)][36]
    __shared__ float s_wx[34];
    __shared__ int   s_xo[34];
    __shared__ float s_wy[3];
    __shared__ int   s_yo[3];
    int bid = blockIdx.x;                // 1152: bg*288 + oy*3 + xc
    int bg = bid / 288; int rem = bid % 288; int oy = rem / 3; int xc = rem % 3;
    int xbase = xc*32;
    const float* qb = g_q + (size_t)bg*K_SLAB;
    int t = threadIdx.x;                 // 256
    int w = t >> 5, lane = t & 31;
    const float R = 47.0f/95.0f;
    if (t < 34) {
        int gx = xbase + t - 1;
        if ((unsigned)gx < 96u) {
            float xsf = gx*R;
            int x0 = min((int)xsf, 46);
            s_wx[t] = xsf - (float)x0;
            s_xo[t] = x0*32;
        } else s_xo[t] = (int)0x80000000;
    } else if (t < 37) {
        int dy = t - 34;
        int ny = oy + dy - 1;
        if ((unsigned)ny < 96u) {
            float ysf = ny*R;
            int y0 = min((int)ysf, 46);
            s_wy[dy] = ysf - (float)y0;
            s_yo[dy] = y0*1536;
        } else s_yo[dy] = (int)0x80000000;
    }
    __syncthreads();
    for (int r = w; r < 102; r += 8) {
        int dy = (r >= 68) ? 2 : ((r >= 34) ? 1 : 0);
        int xx = r - dy*34;
        int yo = s_yo[dy], xo = s_xo[xx];
        float v = 0.f;
        if ((yo | xo) >= 0) {
            float wy = s_wy[dy], wx = s_wx[xx];
            int b00 = yo + xo + lane;
            float qa = qb[b00], qbv = qb[b00+32], qc = qb[b00+1536], qd = qb[b00+1568];
            v = qa*(1.f-wy)*(1.f-wx) + qbv*(1.f-wy)*wx + qc*wy*(1.f-wx) + qd*wy*wx;
        }
        sq[lane*108 + dy*36 + xx] = v;
    }
    __syncthreads();
    float wreg[9];
    #pragma unroll
    for (int k = 0; k < 9; k++) wreg[k] = dw_w[lane*9 + k];
    float lg = offg[lane], lb = offb[lane];
    int w4 = w*4;
    float acc[4] = {0.f, 0.f, 0.f, 0.f};
    #pragma unroll
    for (int ky = 0; ky < 3; ky++) {
        const float* row = &sq[lane*108 + ky*36 + w4];
        float4 a = *(const float4*)row;
        float2 bb = *(const float2*)(row + 4);
        float e0 = a.x, e1 = a.y, e2 = a.z, e3 = a.w, e4 = bb.x, e5 = bb.y;
        float k0 = wreg[ky*3+0], k1 = wreg[ky*3+1], k2 = wreg[ky*3+2];
        acc[0] += e0*k0 + e1*k1 + e2*k2;
        acc[1] += e1*k0 + e2*k1 + e3*k2;
        acc[2] += e2*k0 + e3*k1 + e4*k2;
        acc[3] += e3*k0 + e4*k1 + e5*k2;
    }
    #pragma unroll
    for (int pp = 0; pp < 4; pp++) {
        float av = acc[pp];
        float s = av, q = av*av;
        #pragma unroll
        for (int o = 16; o; o >>= 1) { s += __shfl_xor_sync(0xffffffffu, s, o); q += __shfl_xor_sync(0xffffffffu, q, o); }
        float mu = s*(1.f/32.f);
        float var = q*(1.f/32.f) - mu*mu;
        float rs = rsqrtf(var + 1e-5f);
        float v = (av - mu)*rs*lg + lb;
        float ge = 0.5f*v*(1.f + erff(v*0.70710678118654752f));
        g_t[(size_t)bg*NPIX*32 + (oy*96 + xbase + w4 + pp)*32 + lane] = ge;
    }
}

// ---------------- k5: offset conv 3x3 (32->18) + coords, j-split --------------
// grid 1536: (bg, oy, xh, jhalf). Each block: 48 px, 5 j's (j0 = jhalf*4; j=4 overlaps).
// 256 threads: pg = t>>4 (3 px), half = t&1, cl = (t>>1)&7 (4 ch); shfl-combine.
__global__ void __launch_bounds__(256, 5) k5_off(const float* __restrict__ off_b)
{
    __shared__ float st[150*40];         // 24 KB, [pos][c] pad40
    __shared__ float sw[2*9*5*32];       // 11.5 KB, [half][k][jj(5)][c]
    __shared__ int s_row[3];
    int bid = blockIdx.x;                // 1536: bg*384 + (oy*2+xh)*2 + jhalf
    int bg = bid / 384; int rem = bid % 384;
    int jhalf = rem & 1; int pxg = rem >> 1;
    int oy = pxg >> 1; int xh = pxg & 1;
    int xbase = xh*48;
    int j0 = jhalf*4;
    int t = threadIdx.x;                 // 256
    int wid = t >> 5, lane = t & 31;
    if (t < 3) {
        int ny = oy + t - 1;
        s_row[t] = ((unsigned)ny < 96u) ? ny*96*32 : (int)0x80000000;
    }
    __syncthreads();
    const float* src = g_t + (size_t)bg*NPIX*32;
    for (int r = wid; r < 150; r += 8) {
        int dy = (r >= 100) ? 2 : ((r >= 50) ? 1 : 0);
        int gx = xbase + (r - dy*50) - 1;
        int rb = s_row[dy];
        float v = 0.f;
        if ((rb >= 0) & ((unsigned)gx < 96u)) v = src[rb + gx*32 + lane];
        st[r*40 + lane] = v;
    }
    for (int i = t; i < 2*9*5*32; i += 256) {
        int c = i & 31; int jj = (i >> 5) % 5; int k = (i/160) % 9; int half = i/1440;
        sw[i] = g_w2[((half*9 + k)*9 + (j0 + jj))*32 + c];
    }
    __syncthreads();

    int pg = t >> 4;                     // 0..15 (3 px each)
    int sub = t & 15;
    int half = sub & 1;
    int cl = sub >> 1;                   // 0..7 (4 channels each)
    int px0 = pg*3;                      // local x 0..45
    int c4 = cl*4;
    float acc[3][5];
    #pragma unroll
    for (int p = 0; p < 3; p++)
        #pragma unroll
        for (int j = 0; j < 5; j++) acc[p][j] = 0.f;

    #pragma unroll
    for (int k = 0; k < 9; k++) {
        int ky = k/3, kx = k%3;
        float4 tv[3];
        #pragma unroll
        for (int p = 0; p < 3; p++)
            tv[p] = *(const float4*)&st[(ky*50 + px0 + p + kx)*40 + c4];
        #pragma unroll
        for (int j = 0; j < 5; j++) {
            float4 wv = *(const float4*)&sw[((half*9 + k)*5 + j)*32 + c4];
            #pragma unroll
            for (int p = 0; p < 3; p++)
                acc[p][j] += tv[p].x*wv.x + tv[p].y*wv.y + tv[p].z*wv.z + tv[p].w*wv.w;
        }
    }
    // reduce over cl (lane bits 1..3); stays within 16-lane halves
    #pragma unroll
    for (int p = 0; p < 3; p++)
        #pragma unroll
        for (int j = 0; j < 5; j++) {
            float v = acc[p][j];
            v += __shfl_xor_sync(0xffffffffu, v, 2);
            v += __shfl_xor_sync(0xffffffffu, v, 4);
            v += __shfl_xor_sync(0xffffffffu, v, 8);
            acc[p][j] = v;
        }
    // writers: cl 0..5 -> px_w = cl>>1, jl-range by cl&1
    // jhalf0 owns global j 0..3 (local 0..3): split 2/2; jhalf1 owns j 4..8 (local 0..4): split 3/2
    if (cl < 6) {
        int px_w = cl >> 1;
        int jh2 = cl & 1;
        int js = jh2 ? (jhalf ? 3 : 2) : 0;
        int je = jh2 ? 5 : (jhalf ? 3 : 2);
        int ox = xbase + px0 + px_w;
        int p = oy*96 + ox;
        const float R = 47.0f/95.0f;
        float pos = (half == 0) ? (float)oy : (float)ox;
        for (int jl = js; jl < je; jl++) {
            int j = j0 + jl;
            float pred = acc[px_w][jl] + off_b[j*2 + half];
            float o = tanhf(pred)*11.0f;
            float base = (half == 0) ? (float)(j/3 - 1) : (float)(j%3 - 1);
            float pix  = o + base + pos;
            g_crd[(((size_t)bg*NPIX + p)*9 + j)*2 + half] = pix * R;
        }
    }
}

// ---------------- k6: deformable attention (4 px/warp, 8 lanes/px, fp16 k,v) --
__global__ void k6_attn(const float* __restrict__ rpb, float* __restrict__ out)
{
    __shared__ float so[128*33];         // [ch][px], 16.9 KB
    int bid = blockIdx.x;                // 1152 blocks * 32 px
    int w = threadIdx.x >> 5, lane = threadIdx.x & 31;
    int sub = lane >> 3, ll = lane & 7;
    int bh = bid / 288; int b = bh >> 1, h = bh & 1;
    int prel0 = (bid % 288) * 32;
    int prel = prel0 + w*4 + sub;
    const __half* kbase = g_kh + (size_t)bh*K_SLAB;
    const __half* vbase = g_xh + (size_t)bh*XT_SLAB;
    const float* cp = g_crd + (size_t)bh*NPIX*18 + (size_t)prel*18;

    const float R = 47.0f/95.0f;
    int oy = prel / 96, ox = prel % 96;
    float ys = oy*R, xs = ox*R;
    int yq = min((int)ys, 46), xq = min((int)xs, 46);
    float wyq = ys - (float)yq, wxq = xs - (float)xq;
    const float* qb = g_q + (size_t)bh*K_SLAB;
    int q00 = (yq*48 + xq)*32 + ll*4;
    float4 qa = *(const float4*)&qb[q00];
    float4 qb2 = *(const float4*)&qb[q00+32];
    float4 qc = *(const float4*)&qb[q00+1536];
    float4 qd = *(const float4*)&qb[q00+1568];
    float a00 = (1.f-wyq)*(1.f-wxq), a01 = (1.f-wyq)*wxq, a10 = wyq*(1.f-wxq), a11 = wyq*wxq;
    const float S = 0.1767766952966369f;
    float4 qv;
    qv.x = (qa.x*a00 + qb2.x*a01 + qc.x*a10 + qd.x*a11)*S;
    qv.y = (qa.y*a00 + qb2.y*a01 + qc.y*a10 + qd.y*a11)*S;
    qv.z = (qa.z*a00 + qb2.z*a01 + qc.z*a10 + qd.z*a11)*S;
    qv.w = (qa.w*a00 + qb2.w*a01 + qc.w*a10 + qd.w*a11)*S;

    float a[9], wyA[9], wxA[9];
    int   pkA[9];
    float mx = -1e30f;
    #pragma unroll
    for (int j = 0; j < 9; j++) {
        float iy = cp[2*j], ix = cp[2*j+1];
        float y0f = floorf(iy), x0f = floorf(ix);
        float wy = iy - y0f, wx = ix - x0f;
        int y0 = (int)y0f, x0 = (int)x0f;
        wyA[j] = wy; wxA[j] = wx;
        pkA[j] = (y0 + 16) | ((x0 + 16) << 16);
        bool yi0 = (y0 >= 0) & (y0 < 48);
        bool yi1 = (y0 >= -1) & (y0 < 47);
        bool xi0 = (x0 >= 0) & (x0 < 48);
        bool xi1 = (x0 >= -1) & (x0 < 47);
        float w00 = (yi0 & xi0) ? (1.f-wy)*(1.f-wx) : 0.f;
        float w01 = (yi0 & xi1) ? (1.f-wy)*wx : 0.f;
        float w10 = (yi1 & xi0) ? wy*(1.f-wx) : 0.f;
        float w11 = (yi1 & xi1) ? wy*wx : 0.f;
        int yc0 = max(min(y0, 47), 0), yc1 = max(min(y0+1, 47), 0);
        int xc0 = max(min(x0, 47), 0), xc1 = max(min(x0+1, 47), 0);
        uint2 C00 = *(const uint2*)&kbase[(yc0*48+xc0)*32 + ll*4];
        uint2 C01 = *(const uint2*)&kbase[(yc0*48+xc1)*32 + ll*4];
        uint2 C10 = *(const uint2*)&kbase[(yc1*48+xc0)*32 + ll*4];
        uint2 C11 = *(const uint2*)&kbase[(yc1*48+xc1)*32 + ll*4];
        float2 c00a = __half22float2(*(__half2*)&C00.x), c00b = __half22float2(*(__half2*)&C00.y);
        float2 c01a = __half22float2(*(__half2*)&C01.x), c01b = __half22float2(*(__half2*)&C01.y);
        float2 c10a = __half22float2(*(__half2*)&C10.x), c10b = __half22float2(*(__half2*)&C10.y);
        float2 c11a = __half22float2(*(__half2*)&C11.x), c11b = __half22float2(*(__half2*)&C11.y);
        float4 rv = *(const float4*)&rpb[(h*9 + j)*32 + ll*4];
        float kx0 = c00a.x*w00 + c01a.x*w01 + c10a.x*w10 + c11a.x*w11 + rv.x;
        float kx1 = c00a.y*w00 + c01a.y*w01 + c10a.y*w10 + c11a.y*w11 + rv.y;
        float kx2 = c00b.x*w00 + c01b.x*w01 + c10b.x*w10 + c11b.x*w11 + rv.z;
        float kx3 = c00b.y*w00 + c01b.y*w01 + c10b.y*w10 + c11b.y*w11 + rv.w;
        float d = qv.x*kx0 + qv.y*kx1 + qv.z*kx2 + qv.w*kx3;
        d += __shfl_xor_sync(0xffffffffu, d, 4);
        d += __shfl_xor_sync(0xffffffffu, d, 2);
        d += __shfl_xor_sync(0xffffffffu, d, 1);
        a[j] = d;
        mx = fmaxf(mx, d);
    }
    float ssum = 0.f;
    #pragma unroll
    for (int j = 0; j < 9; j++) { a[j] = __expf(a[j] - mx); ssum += a[j]; }
    float inv = __fdividef(1.f, ssum);

    float acc[16];
    #pragma unroll
    for (int i = 0; i < 16; i++) acc[i] = 0.f;

    #pragma unroll
    for (int j = 0; j < 9; j++) {
        int y0 = (pkA[j] & 0xffff) - 16;
        int x0 = (pkA[j] >> 16) - 16;
        float wy = wyA[j], wx = wxA[j];
        bool yi0 = (y0 >= 0) & (y0 < 48);
        bool yi1 = (y0 >= -1) & (y0 < 47);
        bool xi0 = (x0 >= 0) & (x0 < 48);
        bool xi1 = (x0 >= -1) & (x0 < 47);
        float w00 = (yi0 & xi0) ? (1.f-wy)*(1.f-wx) : 0.f;
        float w01 = (yi0 & xi1) ? (1.f-wy)*wx : 0.f;
        float w10 = (yi1 & xi0) ? wy*(1.f-wx) : 0.f;
        float w11 = (yi1 & xi1) ? wy*wx : 0.f;
        __half2 W00 = __float2half2_rn(w00);
        __half2 W01 = __float2half2_rn(w01);
        __half2 W10 = __float2half2_rn(w10);
        __half2 W11 = __float2half2_rn(w11);
        float aw = a[j]*inv;
        int yc0 = max(min(y0, 47), 0), yc1 = max(min(y0+1, 47), 0);
        int xc0 = max(min(x0, 47), 0), xc1 = max(min(x0+1, 47), 0);
        int r00 = (yc0*48+xc0)*128 + ll*8;
        int r01 = (yc0*48+xc1)*128 + ll*8;
        int r10 = (yc1*48+xc0)*128 + ll*8;
        int r11 = (yc1*48+xc1)*128 + ll*8;
        #pragma unroll
        for (int hb = 0; hb < 2; hb++) {
            int off = hb*64;
            float* ap = acc + hb*8;
            uint4 A00 = *(const uint4*)&vbase[r00 + off];
            uint4 A01 = *(const uint4*)&vbase[r01 + off];
            uint4 A10 = *(const uint4*)&vbase[r10 + off];
            uint4 A11 = *(const uint4*)&vbase[r11 + off];
            const __half2* h00 = (const __half2*)&A00;
            const __half2* h01 = (const __half2*)&A01;
            const __half2* h10 = (const __half2*)&A10;
            const __half2* h11 = (const __half2*)&A11;
            #pragma unroll
            for (int i = 0; i < 4; i++) {
                __half2 m = __hmul2(h00[i], W00);
                m = __hfma2(h01[i], W01, m);
                m = __hfma2(h10[i], W10, m);
                m = __hfma2(h11[i], W11, m);
                float2 f = __half22float2(m);
                ap[2*i+0] += aw*f.x;
                ap[2*i+1] += aw*f.y;
            }
        }
    }
    int pxl = w*4 + sub;
    #pragma unroll
    for (int i = 0; i < 8; i++) {
        so[(ll*8 + i)*33 + pxl]      = acc[i];
        so[(64 + ll*8 + i)*33 + pxl] = acc[8 + i];
    }
    __syncthreads();
    float* ob = out + ((size_t)(b*256 + h*128))*NPIX + prel0;
    for (int idx = threadIdx.x; idx < 4096; idx += 256) {
        int ch = idx >> 5, px = idx & 31;
        ob[(size_t)ch*NPIX + px] = so[ch*33 + px];
    }
}

extern "C" void kernel_launch(void* const* d_in, const int* in_sizes, int n_in,
                              void* d_out, int out_size)
{
    const float* x       = (const float*)d_in[0];
    const float* ln_g    = (const float*)d_in[1];
    const float* ln_b    = (const float*)d_in[2];
    const float* Wq      = (const float*)d_in[3];
    const float* Wk      = (const float*)d_in[4];
    const float* dw_w    = (const float*)d_in[5];
    const float* off_lng = (const float*)d_in[6];
    const float* off_lnb = (const float*)d_in[7];
    const float* off_w   = (const float*)d_in[8];
    const float* off_b   = (const float*)d_in[9];
    const float* rpb     = (const float*)d_in[10];

    k01_prep_tr<<<245, 256>>>(Wq, Wk, ln_g, ln_b, off_w, x);
    k2_qk<<<144, 256>>>();
    k4_dw<<<1152, 256>>>(dw_w, off_lng, off_lnb);
    k5_off<<<1536, 256>>>(off_b);
    k6_attn<<<1152, 256>>>(rpb, (float*)d_out);
}

// round 16
// speedup vs baseline: 1.0533x; 1.0533x over previous
#include <cuda_runtime.h>
#include <cuda_fp16.h>
#include <math.h>

#define HW       2304      // 48*48
#define NPIX     9216      // 96*96
#define XT_SLAB  294912    // 48*48*128
#define K_SLAB   73728     // 48*48*32

__device__ __align__(128) float  g_xt [4*XT_SLAB];  // x channel-last per (b,g) fp32
__device__ __align__(128) __half g_xh [4*XT_SLAB];  // fp16 shadow of v for k6 gather
__device__ __align__(128) __half g_kh [4*K_SLAB];   // k channel-last per (b,g), fp16
__device__ __align__(128) float  g_q  [4*K_SLAB];   // q lowres channel-last
__device__ __align__(128) float  g_t  [4*NPIX*32];  // gelu(ln(dwconv(resize(q))))
__device__ __align__(128) float  g_crd[4*NPIX*18];  // (iy,ix) per (bg,pix,tap)
__device__ float g_mu[2*HW], g_rstd[2*HW];
__device__ __align__(128) float g_WT[256*128];      // [c][o]; o<64: Wq, o>=64: Wk (LN-gain folded)
__device__ float g_csum[128], g_bias2[128];
__device__ __align__(128) float g_w2[2*9*9*32];     // [half][k][j][c]

// ---------------- k01: fused prep (blocks 0-148) + transpose/LN (blocks 149-244)
__global__ void k01_prep_tr(const float* __restrict__ Wq, const float* __restrict__ Wk,
                            const float* __restrict__ g, const float* __restrict__ b,
                            const float* __restrict__ off_w, const float* __restrict__ x)
{
    __shared__ float xs[128*49];
    __shared__ float ssum[48], ssq[48];
    int t = threadIdx.x; // 256
    if (blockIdx.x < 128) {
        int o = blockIdx.x, c = t;
        const float* Wr = (o < 64) ? (Wq + o*256) : (Wk + (o-64)*256);
        float w  = Wr[c];
        float gc = g[c];
        g_WT[c*128 + o] = w*gc;
        float cs = w*gc, bs = w*b[c];
        #pragma unroll
        for (int off = 16; off; off >>= 1) {
            cs += __shfl_xor_sync(0xffffffffu, cs, off);
            bs += __shfl_xor_sync(0xffffffffu, bs, off);
        }
        int wid = c >> 5, lane = c & 31;
        if (lane == 0) { xs[wid] = cs; xs[16 + wid] = bs; }
        __syncthreads();
        if (c == 0) {
            float a = 0.f, bbv = 0.f;
            #pragma unroll
            for (int i = 0; i < 8; i++) { a += xs[i]; bbv += xs[16 + i]; }
            g_csum[o] = a; g_bias2[o] = bbv;
        }
        return;
    }
    if (blockIdx.x < 149) {
        int i = (blockIdx.x - 128)*256 + t;
        if (i < 2*9*9*32) {
            int c = i & 31; int j = (i >> 5) % 9; int k = (i/288) % 9; int half = i/2592;
            g_w2[i] = off_w[((j*2+half)*32 + c)*9 + k];
        }
        return;
    }
    int bid = blockIdx.x - 149;          // 0..95
    int b2 = bid / 48, y = bid % 48;
    if (t < 48) { ssum[t] = 0.f; ssq[t] = 0.f; }
    int wid = t >> 5, lane = t & 31;
    for (int half = 0; half < 2; half++) {
        __syncthreads();
        const float* src = x + ((size_t)(b2*256 + half*128))*HW + y*48;
        for (int idx = t; idx < 128*48; idx += 256) {
            int c = idx / 48, xx = idx - c*48;
            xs[c*49 + xx] = src[(size_t)c*HW + xx];
        }
        __syncthreads();
        for (int xx = wid; xx < 48; xx += 8) {
            float s = 0.f, q = 0.f;
            #pragma unroll
            for (int j = 0; j < 4; j++) { float v = xs[(lane + 32*j)*49 + xx]; s += v; q += v*v; }
            #pragma unroll
            for (int o = 16; o; o >>= 1) { s += __shfl_xor_sync(0xffffffffu, s, o); q += __shfl_xor_sync(0xffffffffu, q, o); }
            if (lane == 0) { ssum[xx] += s; ssq[xx] += q; }
        }
        size_t base = ((size_t)(b2*2 + half))*XT_SLAB + (size_t)y*48*128;
        float*  dst = g_xt + base;
        __half* dsh = g_xh + base;
        for (int idx = t; idx < 128*48; idx += 256) {
            int xx = idx >> 7, c = idx & 127;
            float v = xs[c*49 + xx];
            dst[xx*128 + c] = v;
            dsh[xx*128 + c] = __float2half_rn(v);
        }
    }
    __syncthreads();
    if (t < 48) {
        float mu = ssum[t] * (1.0f/256.0f);
        float var = ssq[t] * (1.0f/256.0f) - mu*mu;
        int p = b2*HW + y*48 + t;
        g_mu[p] = mu;
        g_rstd[p] = rsqrtf(var + 1e-5f);
    }
}

// ---------------- k2: Q/K projection (2px x 8out per thread) ------------------
__global__ void k2_qk()
{
    int t = threadIdx.x;                 // 256
    int og = t & 15, pg = t >> 4;        // 16 px-groups x 2 px
    int P0 = blockIdx.x*32 + pg*2;       // 0..4606
    int b = P0 / HW, p0 = P0 % HW;
    int o0 = og*8;
    const float* xA = g_xt + (size_t)(b*2)*XT_SLAB + (size_t)p0*128;
    float accA[8], accB[8];
    #pragma unroll
    for (int j = 0; j < 8; j++) { accA[j] = 0.f; accB[j] = 0.f; }

    for (int h2 = 0; h2 < 2; h2++) {
        const float4* xpA = (const float4*)(xA + (size_t)h2*XT_SLAB);
        const float4* xpB = xpA + 32;
        #pragma unroll 4
        for (int c4 = 0; c4 < 32; c4++) {
            float4 xa = xpA[c4];
            float4 xb = xpB[c4];
            const float* wb = &g_WT[(h2*128 + c4*4)*128 + o0];
            #pragma unroll
            for (int cc = 0; cc < 4; cc++) {
                float4 w0 = *(const float4*)&wb[cc*128];
                float4 w1 = *(const float4*)&wb[cc*128 + 4];
                float va = (cc == 0) ? xa.x : (cc == 1) ? xa.y : (cc == 2) ? xa.z : xa.w;
                float vb = (cc == 0) ? xb.x : (cc == 1) ? xb.y : (cc == 2) ? xb.z : xb.w;
                accA[0] += va*w0.x; accA[1] += va*w0.y; accA[2] += va*w0.z; accA[3] += va*w0.w;
                accA[4] += va*w1.x; accA[5] += va*w1.y; accA[6] += va*w1.z; accA[7] += va*w1.w;
                accB[0] += vb*w0.x; accB[1] += vb*w0.y; accB[2] += vb*w0.z; accB[3] += vb*w0.w;
                accB[4] += vb*w1.x; accB[5] += vb*w1.y; accB[6] += vb*w1.z; accB[7] += vb*w1.w;
            }
        }
    }
    int isK = (o0 >= 64);
    int oo  = o0 & 63;
    int grp = oo >> 5, cl0 = oo & 31;
    #pragma unroll
    for (int px = 0; px < 2; px++) {
        float* acc = px ? accB : accA;
        int p = p0 + px;
        float mu = g_mu[b*HW + p], rs = g_rstd[b*HW + p];
        float vv[8];
        #pragma unroll
        for (int j = 0; j < 8; j++)
            vv[j] = rs*(acc[j] - mu*g_csum[o0+j]) + g_bias2[o0+j];
        if (isK) {
            __half* dsth = g_kh + (size_t)(b*2 + grp)*K_SLAB + (size_t)p*32 + cl0;
            __half2 h0 = __floats2half2_rn(vv[0], vv[1]);
            __half2 h1 = __floats2half2_rn(vv[2], vv[3]);
            __half2 h2 = __floats2half2_rn(vv[4], vv[5]);
            __half2 h3 = __floats2half2_rn(vv[6], vv[7]);
            uint4 pk;
            pk.x = *(unsigned*)&h0; pk.y = *(unsigned*)&h1;
            pk.z = *(unsigned*)&h2; pk.w = *(unsigned*)&h3;
            *(uint4*)dsth = pk;
        } else {
            float* dst = g_q + (size_t)(b*2 + grp)*K_SLAB + (size_t)p*32 + cl0;
            *(float4*)&dst[0] = make_float4(vv[0], vv[1], vv[2], vv[3]);
            *(float4*)&dst[4] = make_float4(vv[4], vv[5], vv[6], vv[7]);
        }
    }
}

// ---------------- k4: inline resize + depthwise 3x3 + channel-LN + GeLU -------
__global__ void k4_dw(const float* __restrict__ dw_w,
                      const float* __restrict__ offg, const float* __restrict__ offb)
{
    __shared__ float sq[32*108];         // 13.8 KB, [c][ky(3)][36]
    __shared__ float s_wx[34];
    __shared__ int   s_xo[34];
    __shared__ float s_wy[3];
    __shared__ int   s_yo[3];
    int bid = blockIdx.x;                // 1152: bg*288 + oy*3 + xc
    int bg = bid / 288; int rem = bid % 288; int oy = rem / 3; int xc = rem % 3;
    int xbase = xc*32;
    const float* qb = g_q + (size_t)bg*K_SLAB;
    int t = threadIdx.x;                 // 256
    int w = t >> 5, lane = t & 31;
    const float R = 47.0f/95.0f;
    if (t < 34) {
        int gx = xbase + t - 1;
        if ((unsigned)gx < 96u) {
            float xsf = gx*R;
            int x0 = min((int)xsf, 46);
            s_wx[t] = xsf - (float)x0;
            s_xo[t] = x0*32;
        } else s_xo[t] = (int)0x80000000;
    } else if (t < 37) {
        int dy = t - 34;
        int ny = oy + dy - 1;
        if ((unsigned)ny < 96u) {
            float ysf = ny*R;
            int y0 = min((int)ysf, 46);
            s_wy[dy] = ysf - (float)y0;
            s_yo[dy] = y0*1536;
        } else s_yo[dy] = (int)0x80000000;
    }
    __syncthreads();
    for (int r = w; r < 102; r += 8) {
        int dy = (r >= 68) ? 2 : ((r >= 34) ? 1 : 0);
        int xx = r - dy*34;
        int yo = s_yo[dy], xo = s_xo[xx];
        float v = 0.f;
        if ((yo | xo) >= 0) {
            float wy = s_wy[dy], wx = s_wx[xx];
            int b00 = yo + xo + lane;
            float qa = qb[b00], qbv = qb[b00+32], qc = qb[b00+1536], qd = qb[b00+1568];
            v = qa*(1.f-wy)*(1.f-wx) + qbv*(1.f-wy)*wx + qc*wy*(1.f-wx) + qd*wy*wx;
        }
        sq[lane*108 + dy*36 + xx] = v;
    }
    __syncthreads();
    float wreg[9];
    #pragma unroll
    for (int k = 0; k < 9; k++) wreg[k] = dw_w[lane*9 + k];
    float lg = offg[lane], lb = offb[lane];
    int w4 = w*4;
    float acc[4] = {0.f, 0.f, 0.f, 0.f};
    #pragma unroll
    for (int ky = 0; ky < 3; ky++) {
        const float* row = &sq[lane*108 + ky*36 + w4];
        float4 a = *(const float4*)row;
        float2 bb = *(const float2*)(row + 4);
        float e0 = a.x, e1 = a.y, e2 = a.z, e3 = a.w, e4 = bb.x, e5 = bb.y;
        float k0 = wreg[ky*3+0], k1 = wreg[ky*3+1], k2 = wreg[ky*3+2];
        acc[0] += e0*k0 + e1*k1 + e2*k2;
        acc[1] += e1*k0 + e2*k1 + e3*k2;
        acc[2] += e2*k0 + e3*k1 + e4*k2;
        acc[3] += e3*k0 + e4*k1 + e5*k2;
    }
    #pragma unroll
    for (int pp = 0; pp < 4; pp++) {
        float av = acc[pp];
        float s = av, q = av*av;
        #pragma unroll
        for (int o = 16; o; o >>= 1) { s += __shfl_xor_sync(0xffffffffu, s, o); q += __shfl_xor_sync(0xffffffffu, q, o); }
        float mu = s*(1.f/32.f);
        float var = q*(1.f/32.f) - mu*mu;
        float rs = rsqrtf(var + 1e-5f);
        float v = (av - mu)*rs*lg + lb;
        float ge = 0.5f*v*(1.f + erff(v*0.70710678118654752f));
        g_t[(size_t)bg*NPIX*32 + (oy*96 + xbase + w4 + pp)*32 + lane] = ge;
    }
}

// ---------------- k5: offset conv 3x3 (32->18) + coords (R11/R14 config) ------
// grid 768 (half-row, 48 px), 256 threads, 4 blocks/SM.
// pg = t>>4 (3 px each), half = t&1, cl = (t>>1)&7 (4 ch each); shfl-combine.
__global__ void __launch_bounds__(256, 4) k5_off(const float* __restrict__ off_b)
{
    __shared__ float st[150*40];         // 24 KB, [pos][c] pad40
    __shared__ float sw[2*9*9*32];       // 20.7 KB, [half][k][j][c]
    __shared__ int s_row[3];
    int bid = blockIdx.x;                // 768: bg*192 + oy*2 + xh
    int bg = bid / 192; int rem = bid % 192; int oy = rem >> 1; int xh = rem & 1;
    int xbase = xh*48;
    int t = threadIdx.x;                 // 256
    int wid = t >> 5, lane = t & 31;
    if (t < 3) {
        int ny = oy + t - 1;
        s_row[t] = ((unsigned)ny < 96u) ? ny*96*32 : (int)0x80000000;
    }
    __syncthreads();
    const float* src = g_t + (size_t)bg*NPIX*32;
    for (int r = wid; r < 150; r += 8) {
        int dy = (r >= 100) ? 2 : ((r >= 50) ? 1 : 0);
        int gx = xbase + (r - dy*50) - 1;
        int rb = s_row[dy];
        float v = 0.f;
        if ((rb >= 0) & ((unsigned)gx < 96u)) v = src[rb + gx*32 + lane];
        st[r*40 + lane] = v;
    }
    for (int i = t; i < 2*9*9*32; i += 256) sw[i] = g_w2[i];
    __syncthreads();

    int pg = t >> 4;                     // 0..15 (3 px each)
    int sub = t & 15;
    int half = sub & 1;
    int cl = sub >> 1;                   // 0..7 (4 channels each)
    int px0 = pg*3;                      // local x 0..45
    int c4 = cl*4;
    float acc[3][9];
    #pragma unroll
    for (int p = 0; p < 3; p++)
        #pragma unroll
        for (int j = 0; j < 9; j++) acc[p][j] = 0.f;

    #pragma unroll
    for (int k = 0; k < 9; k++) {
        int ky = k/3, kx = k%3;
        float4 tv[3];
        #pragma unroll
        for (int p = 0; p < 3; p++)
            tv[p] = *(const float4*)&st[(ky*50 + px0 + p + kx)*40 + c4];
        #pragma unroll
        for (int j = 0; j < 9; j++) {
            float4 wv = *(const float4*)&sw[((half*9 + k)*9 + j)*32 + c4];
            #pragma unroll
            for (int p = 0; p < 3; p++)
                acc[p][j] += tv[p].x*wv.x + tv[p].y*wv.y + tv[p].z*wv.z + tv[p].w*wv.w;
        }
    }
    // reduce over cl (lane bits 1..3); stays within 16-lane halves
    #pragma unroll
    for (int p = 0; p < 3; p++)
        #pragma unroll
        for (int j = 0; j < 9; j++) {
            float v = acc[p][j];
            v += __shfl_xor_sync(0xffffffffu, v, 2);
            v += __shfl_xor_sync(0xffffffffu, v, 4);
            v += __shfl_xor_sync(0xffffffffu, v, 8);
            acc[p][j] = v;
        }
    // writers: cl 0..5 -> px_w = cl>>1, j-range by cl&1
    if (cl < 6) {
        int px_w = cl >> 1;
        int jh = cl & 1;
        int ox = xbase + px0 + px_w;
        int p = oy*96 + ox;
        const float R = 47.0f/95.0f;
        int j0 = jh ? 5 : 0, j1 = jh ? 9 : 5;
        float pos = (half == 0) ? (float)oy : (float)ox;
        for (int j = j0; j < j1; j++) {
            float pred = acc[px_w][j] + off_b[j*2 + half];
            float o = tanhf(pred)*11.0f;
            float base = (half == 0) ? (float)(j/3 - 1) : (float)(j%3 - 1);
            float pix  = o + base + pos;
            g_crd[(((size_t)bg*NPIX + p)*9 + j)*2 + half] = pix * R;
        }
    }
}

// ---------------- k6: deformable attention (4 px/warp, 8 lanes/px, fp16 k,v) --
__global__ void k6_attn(const float* __restrict__ rpb, float* __restrict__ out)
{
    __shared__ float so[128*33];         // [ch][px], 16.9 KB
    int bid = blockIdx.x;                // 1152 blocks * 32 px
    int w = threadIdx.x >> 5, lane = threadIdx.x & 31;
    int sub = lane >> 3, ll = lane & 7;
    int bh = bid / 288; int b = bh >> 1, h = bh & 1;
    int prel0 = (bid % 288) * 32;
    int prel = prel0 + w*4 + sub;
    const __half* kbase = g_kh + (size_t)bh*K_SLAB;
    const __half* vbase = g_xh + (size_t)bh*XT_SLAB;
    const float* cp = g_crd + (size_t)bh*NPIX*18 + (size_t)prel*18;

    const float R = 47.0f/95.0f;
    int oy = prel / 96, ox = prel % 96;
    float ys = oy*R, xs = ox*R;
    int yq = min((int)ys, 46), xq = min((int)xs, 46);
    float wyq = ys - (float)yq, wxq = xs - (float)xq;
    const float* qb = g_q + (size_t)bh*K_SLAB;
    int q00 = (yq*48 + xq)*32 + ll*4;
    float4 qa = *(const float4*)&qb[q00];
    float4 qb2 = *(const float4*)&qb[q00+32];
    float4 qc = *(const float4*)&qb[q00+1536];
    float4 qd = *(const float4*)&qb[q00+1568];
    float a00 = (1.f-wyq)*(1.f-wxq), a01 = (1.f-wyq)*wxq, a10 = wyq*(1.f-wxq), a11 = wyq*wxq;
    const float S = 0.1767766952966369f;
    float4 qv;
    qv.x = (qa.x*a00 + qb2.x*a01 + qc.x*a10 + qd.x*a11)*S;
    qv.y = (qa.y*a00 + qb2.y*a01 + qc.y*a10 + qd.y*a11)*S;
    qv.z = (qa.z*a00 + qb2.z*a01 + qc.z*a10 + qd.z*a11)*S;
    qv.w = (qa.w*a00 + qb2.w*a01 + qc.w*a10 + qd.w*a11)*S;

    float a[9], wyA[9], wxA[9];
    int   pkA[9];
    float mx = -1e30f;
    #pragma unroll
    for (int j = 0; j < 9; j++) {
        float iy = cp[2*j], ix = cp[2*j+1];
        float y0f = floorf(iy), x0f = floorf(ix);
        float wy = iy - y0f, wx = ix - x0f;
        int y0 = (int)y0f, x0 = (int)x0f;
        wyA[j] = wy; wxA[j] = wx;
        pkA[j] = (y0 + 16) | ((x0 + 16) << 16);
        bool yi0 = (y0 >= 0) & (y0 < 48);
        bool yi1 = (y0 >= -1) & (y0 < 47);
        bool xi0 = (x0 >= 0) & (x0 < 48);
        bool xi1 = (x0 >= -1) & (x0 < 47);
        float w00 = (yi0 & xi0) ? (1.f-wy)*(1.f-wx) : 0.f;
        float w01 = (yi0 & xi1) ? (1.f-wy)*wx : 0.f;
        float w10 = (yi1 & xi0) ? wy*(1.f-wx) : 0.f;
        float w11 = (yi1 & xi1) ? wy*wx : 0.f;
        int yc0 = max(min(y0, 47), 0), yc1 = max(min(y0+1, 47), 0);
        int xc0 = max(min(x0, 47), 0), xc1 = max(min(x0+1, 47), 0);
        uint2 C00 = *(const uint2*)&kbase[(yc0*48+xc0)*32 + ll*4];
        uint2 C01 = *(const uint2*)&kbase[(yc0*48+xc1)*32 + ll*4];
        uint2 C10 = *(const uint2*)&kbase[(yc1*48+xc0)*32 + ll*4];
        uint2 C11 = *(const uint2*)&kbase[(yc1*48+xc1)*32 + ll*4];
        float2 c00a = __half22float2(*(__half2*)&C00.x), c00b = __half22float2(*(__half2*)&C00.y);
        float2 c01a = __half22float2(*(__half2*)&C01.x), c01b = __half22float2(*(__half2*)&C01.y);
        float2 c10a = __half22float2(*(__half2*)&C10.x), c10b = __half22float2(*(__half2*)&C10.y);
        float2 c11a = __half22float2(*(__half2*)&C11.x), c11b = __half22float2(*(__half2*)&C11.y);
        float4 rv = *(const float4*)&rpb[(h*9 + j)*32 + ll*4];
        float kx0 = c00a.x*w00 + c01a.x*w01 + c10a.x*w10 + c11a.x*w11 + rv.x;
        float kx1 = c00a.y*w00 + c01a.y*w01 + c10a.y*w10 + c11a.y*w11 + rv.y;
        float kx2 = c00b.x*w00 + c01b.x*w01 + c10b.x*w10 + c11b.x*w11 + rv.z;
        float kx3 = c00b.y*w00 + c01b.y*w01 + c10b.y*w10 + c11b.y*w11 + rv.w;
        float d = qv.x*kx0 + qv.y*kx1 + qv.z*kx2 + qv.w*kx3;
        d += __shfl_xor_sync(0xffffffffu, d, 4);
        d += __shfl_xor_sync(0xffffffffu, d, 2);
        d += __shfl_xor_sync(0xffffffffu, d, 1);
        a[j] = d;
        mx = fmaxf(mx, d);
    }
    float ssum = 0.f;
    #pragma unroll
    for (int j = 0; j < 9; j++) { a[j] = __expf(a[j] - mx); ssum += a[j]; }
    float inv = __fdividef(1.f, ssum);

    float acc[16];
    #pragma unroll
    for (int i = 0; i < 16; i++) acc[i] = 0.f;

    #pragma unroll
    for (int j = 0; j < 9; j++) {
        int y0 = (pkA[j] & 0xffff) - 16;
        int x0 = (pkA[j] >> 16) - 16;
        float wy = wyA[j], wx = wxA[j];
        bool yi0 = (y0 >= 0) & (y0 < 48);
        bool yi1 = (y0 >= -1) & (y0 < 47);
        bool xi0 = (x0 >= 0) & (x0 < 48);
        bool xi1 = (x0 >= -1) & (x0 < 47);
        float w00 = (yi0 & xi0) ? (1.f-wy)*(1.f-wx) : 0.f;
        float w01 = (yi0 & xi1) ? (1.f-wy)*wx : 0.f;
        float w10 = (yi1 & xi0) ? wy*(1.f-wx) : 0.f;
        float w11 = (yi1 & xi1) ? wy*wx : 0.f;
        __half2 W00 = __float2half2_rn(w00);
        __half2 W01 = __float2half2_rn(w01);
        __half2 W10 = __float2half2_rn(w10);
        __half2 W11 = __float2half2_rn(w11);
        float aw = a[j]*inv;
        int yc0 = max(min(y0, 47), 0), yc1 = max(min(y0+1, 47), 0);
        int xc0 = max(min(x0, 47), 0), xc1 = max(min(x0+1, 47), 0);
        int r00 = (yc0*48+xc0)*128 + ll*8;
        int r01 = (yc0*48+xc1)*128 + ll*8;
        int r10 = (yc1*48+xc0)*128 + ll*8;
        int r11 = (yc1*48+xc1)*128 + ll*8;
        #pragma unroll
        for (int hb = 0; hb < 2; hb++) {
            int off = hb*64;
            float* ap = acc + hb*8;
            uint4 A00 = *(const uint4*)&vbase[r00 + off];
            uint4 A01 = *(const uint4*)&vbase[r01 + off];
            uint4 A10 = *(const uint4*)&vbase[r10 + off];
            uint4 A11 = *(const uint4*)&vbase[r11 + off];
            const __half2* h00 = (const __half2*)&A00;
            const __half2* h01 = (const __half2*)&A01;
            const __half2* h10 = (const __half2*)&A10;
            const __half2* h11 = (const __half2*)&A11;
            #pragma unroll
            for (int i = 0; i < 4; i++) {
                __half2 m = __hmul2(h00[i], W00);
                m = __hfma2(h01[i], W01, m);
                m = __hfma2(h10[i], W10, m);
                m = __hfma2(h11[i], W11, m);
                float2 f = __half22float2(m);
                ap[2*i+0] += aw*f.x;
                ap[2*i+1] += aw*f.y;
            }
        }
    }
    int pxl = w*4 + sub;
    #pragma unroll
    for (int i = 0; i < 8; i++) {
        so[(ll*8 + i)*33 + pxl]      = acc[i];
        so[(64 + ll*8 + i)*33 + pxl] = acc[8 + i];
    }
    __syncthreads();
    float* ob = out + ((size_t)(b*256 + h*128))*NPIX + prel0;
    for (int idx = threadIdx.x; idx < 4096; idx += 256) {
        int ch = idx >> 5, px = idx & 31;
        ob[(size_t)ch*NPIX + px] = so[ch*33 + px];
    }
}

extern "C" void kernel_launch(void* const* d_in, const int* in_sizes, int n_in,
                              void* d_out, int out_size)
{
    const float* x       = (const float*)d_in[0];
    const float* ln_g    = (const float*)d_in[1];
    const float* ln_b    = (const float*)d_in[2];
    const float* Wq      = (const float*)d_in[3];
    const float* Wk      = (const float*)d_in[4];
    const float* dw_w    = (const float*)d_in[5];
    const float* off_lng = (const float*)d_in[6];
    const float* off_lnb = (const float*)d_in[7];
    const float* off_w   = (const float*)d_in[8];
    const float* off_b   = (const float*)d_in[9];
    const float* rpb     = (const float*)d_in[10];

    k01_prep_tr<<<245, 256>>>(Wq, Wk, ln_g, ln_b, off_w, x);
    k2_qk<<<144, 256>>>();
    k4_dw<<<1152, 256>>>(dw_w, off_lng, off_lnb);
    k5_off<<<768, 256>>>(off_b);
    k6_attn<<<1152, 256>>>(rpb, (float*)d_out);
}

// round 17
// speedup vs baseline: 1.0565x; 1.0030x over previous
#include <cuda_runtime.h>
#include <cuda_fp16.h>
#include <math.h>

#define HW       2304      // 48*48
#define NPIX     9216      // 96*96
#define XT_SLAB  294912    // 48*48*128
#define K_SLAB   73728     // 48*48*32

__device__ __align__(128) float  g_xt [4*XT_SLAB];  // x channel-last per (b,g) fp32
__device__ __align__(128) __half g_xh [4*XT_SLAB];  // fp16 shadow of v for k6 gather
__device__ __align__(128) __half g_kh [4*K_SLAB];   // k channel-last per (b,g), fp16
__device__ __align__(128) float  g_q  [4*K_SLAB];   // q lowres channel-last
__device__ __align__(128) float  g_t  [4*NPIX*32];  // gelu(ln(dwconv(resize(q))))
__device__ __align__(128) float  g_crd[4*NPIX*18];  // (iy,ix) per (bg,pix,tap)
__device__ float g_mu[2*HW], g_rstd[2*HW];
__device__ __align__(128) float g_WT[256*128];      // [c][o]; o<64: Wq, o>=64: Wk (LN-gain folded)
__device__ float g_csum[128], g_bias2[128];
__device__ __align__(128) float g_w2[2*9*9*32];     // [half][k][j][c]

// ---------------- k01: fused prep (blocks 0-148) + transpose/LN (blocks 149-244)
__global__ void k01_prep_tr(const float* __restrict__ Wq, const float* __restrict__ Wk,
                            const float* __restrict__ g, const float* __restrict__ b,
                            const float* __restrict__ off_w, const float* __restrict__ x)
{
    __shared__ float xs[128*49];
    __shared__ float ssum[48], ssq[48];
    int t = threadIdx.x; // 256
    if (blockIdx.x < 128) {
        int o = blockIdx.x, c = t;
        const float* Wr = (o < 64) ? (Wq + o*256) : (Wk + (o-64)*256);
        float w  = Wr[c];
        float gc = g[c];
        g_WT[c*128 + o] = w*gc;
        float cs = w*gc, bs = w*b[c];
        #pragma unroll
        for (int off = 16; off; off >>= 1) {
            cs += __shfl_xor_sync(0xffffffffu, cs, off);
            bs += __shfl_xor_sync(0xffffffffu, bs, off);
        }
        int wid = c >> 5, lane = c & 31;
        if (lane == 0) { xs[wid] = cs; xs[16 + wid] = bs; }
        __syncthreads();
        if (c == 0) {
            float a = 0.f, bbv = 0.f;
            #pragma unroll
            for (int i = 0; i < 8; i++) { a += xs[i]; bbv += xs[16 + i]; }
            g_csum[o] = a; g_bias2[o] = bbv;
        }
        return;
    }
    if (blockIdx.x < 149) {
        int i = (blockIdx.x - 128)*256 + t;
        if (i < 2*9*9*32) {
            int c = i & 31; int j = (i >> 5) % 9; int k = (i/288) % 9; int half = i/2592;
            g_w2[i] = off_w[((j*2+half)*32 + c)*9 + k];
        }
        return;
    }
    int bid = blockIdx.x - 149;          // 0..95
    int b2 = bid / 48, y = bid % 48;
    if (t < 48) { ssum[t] = 0.f; ssq[t] = 0.f; }
    int wid = t >> 5, lane = t & 31;
    for (int half = 0; half < 2; half++) {
        __syncthreads();
        const float* src = x + ((size_t)(b2*256 + half*128))*HW + y*48;
        for (int idx = t; idx < 128*12; idx += 256) {
            int c = idx / 12, x4 = idx % 12;
            float4 v = *(const float4*)&src[(size_t)c*HW + x4*4];
            float* d = &xs[c*49 + x4*4];
            d[0] = v.x; d[1] = v.y; d[2] = v.z; d[3] = v.w;
        }
        __syncthreads();
        for (int xx = wid; xx < 48; xx += 8) {
            float s = 0.f, q = 0.f;
            #pragma unroll
            for (int j = 0; j < 4; j++) { float v = xs[(lane + 32*j)*49 + xx]; s += v; q += v*v; }
            #pragma unroll
            for (int o = 16; o; o >>= 1) { s += __shfl_xor_sync(0xffffffffu, s, o); q += __shfl_xor_sync(0xffffffffu, q, o); }
            if (lane == 0) { ssum[xx] += s; ssq[xx] += q; }
        }
        size_t base = ((size_t)(b2*2 + half))*XT_SLAB + (size_t)y*48*128;
        float*  dst = g_xt + base;
        __half* dsh = g_xh + base;
        for (int idx = t; idx < 128*48; idx += 256) {
            int xx = idx >> 7, c = idx & 127;
            float v = xs[c*49 + xx];
            dst[xx*128 + c] = v;
            dsh[xx*128 + c] = __float2half_rn(v);
        }
    }
    __syncthreads();
    if (t < 48) {
        float mu = ssum[t] * (1.0f/256.0f);
        float var = ssq[t] * (1.0f/256.0f) - mu*mu;
        int p = b2*HW + y*48 + t;
        g_mu[p] = mu;
        g_rstd[p] = rsqrtf(var + 1e-5f);
    }
}

// ---------------- k2: Q/K projection (2px x 8out per thread) ------------------
__global__ void k2_qk()
{
    int t = threadIdx.x;                 // 256
    int og = t & 15, pg = t >> 4;        // 16 px-groups x 2 px
    int P0 = blockIdx.x*32 + pg*2;       // 0..4606
    int b = P0 / HW, p0 = P0 % HW;
    int o0 = og*8;
    const float* xA = g_xt + (size_t)(b*2)*XT_SLAB + (size_t)p0*128;
    float accA[8], accB[8];
    #pragma unroll
    for (int j = 0; j < 8; j++) { accA[j] = 0.f; accB[j] = 0.f; }

    for (int h2 = 0; h2 < 2; h2++) {
        const float4* xpA = (const float4*)(xA + (size_t)h2*XT_SLAB);
        const float4* xpB = xpA + 32;
        #pragma unroll 4
        for (int c4 = 0; c4 < 32; c4++) {
            float4 xa = xpA[c4];
            float4 xb = xpB[c4];
            const float* wb = &g_WT[(h2*128 + c4*4)*128 + o0];
            #pragma unroll
            for (int cc = 0; cc < 4; cc++) {
                float4 w0 = *(const float4*)&wb[cc*128];
                float4 w1 = *(const float4*)&wb[cc*128 + 4];
                float va = (cc == 0) ? xa.x : (cc == 1) ? xa.y : (cc == 2) ? xa.z : xa.w;
                float vb = (cc == 0) ? xb.x : (cc == 1) ? xb.y : (cc == 2) ? xb.z : xb.w;
                accA[0] += va*w0.x; accA[1] += va*w0.y; accA[2] += va*w0.z; accA[3] += va*w0.w;
                accA[4] += va*w1.x; accA[5] += va*w1.y; accA[6] += va*w1.z; accA[7] += va*w1.w;
                accB[0] += vb*w0.x; accB[1] += vb*w0.y; accB[2] += vb*w0.z; accB[3] += vb*w0.w;
                accB[4] += vb*w1.x; accB[5] += vb*w1.y; accB[6] += vb*w1.z; accB[7] += vb*w1.w;
            }
        }
    }
    int isK = (o0 >= 64);
    int oo  = o0 & 63;
    int grp = oo >> 5, cl0 = oo & 31;
    #pragma unroll
    for (int px = 0; px < 2; px++) {
        float* acc = px ? accB : accA;
        int p = p0 + px;
        float mu = g_mu[b*HW + p], rs = g_rstd[b*HW + p];
        float vv[8];
        #pragma unroll
        for (int j = 0; j < 8; j++)
            vv[j] = rs*(acc[j] - mu*g_csum[o0+j]) + g_bias2[o0+j];
        if (isK) {
            __half* dsth = g_kh + (size_t)(b*2 + grp)*K_SLAB + (size_t)p*32 + cl0;
            __half2 h0 = __floats2half2_rn(vv[0], vv[1]);
            __half2 h1 = __floats2half2_rn(vv[2], vv[3]);
            __half2 h2 = __floats2half2_rn(vv[4], vv[5]);
            __half2 h3 = __floats2half2_rn(vv[6], vv[7]);
            uint4 pk;
            pk.x = *(unsigned*)&h0; pk.y = *(unsigned*)&h1;
            pk.z = *(unsigned*)&h2; pk.w = *(unsigned*)&h3;
            *(uint4*)dsth = pk;
        } else {
            float* dst = g_q + (size_t)(b*2 + grp)*K_SLAB + (size_t)p*32 + cl0;
            *(float4*)&dst[0] = make_float4(vv[0], vv[1], vv[2], vv[3]);
            *(float4*)&dst[4] = make_float4(vv[4], vv[5], vv[6], vv[7]);
        }
    }
}

// ---------------- k4: inline resize + depthwise 3x3 + channel-LN + GeLU -------
__global__ void k4_dw(const float* __restrict__ dw_w,
                      const float* __restrict__ offg, const float* __restrict__ offb)
{
    __shared__ float sq[32*108];         // 13.8 KB, [c][ky(3)][36]
    __shared__ float s_wx[34];
    __shared__ int   s_xo[34];
    __shared__ float s_wy[3];
    __shared__ int   s_yo[3];
    int bid = blockIdx.x;                // 1152: bg*288 + oy*3 + xc
    int bg = bid / 288; int rem = bid % 288; int oy = rem / 3; int xc = rem % 3;
    int xbase = xc*32;
    const float* qb = g_q + (size_t)bg*K_SLAB;
    int t = threadIdx.x;                 // 256
    int w = t >> 5, lane = t & 31;
    const float R = 47.0f/95.0f;
    if (t < 34) {
        int gx = xbase + t - 1;
        if ((unsigned)gx < 96u) {
            float xsf = gx*R;
            int x0 = min((int)xsf, 46);
            s_wx[t] = xsf - (float)x0;
            s_xo[t] = x0*32;
        } else s_xo[t] = (int)0x80000000;
    } else if (t < 37) {
        int dy = t - 34;
        int ny = oy + dy - 1;
        if ((unsigned)ny < 96u) {
            float ysf = ny*R;
            int y0 = min((int)ysf, 46);
            s_wy[dy] = ysf - (float)y0;
            s_yo[dy] = y0*1536;
        } else s_yo[dy] = (int)0x80000000;
    }
    __syncthreads();
    for (int r = w; r < 102; r += 8) {
        int dy = (r >= 68) ? 2 : ((r >= 34) ? 1 : 0);
        int xx = r - dy*34;
        int yo = s_yo[dy], xo = s_xo[xx];
        float v = 0.f;
        if ((yo | xo) >= 0) {
            float wy = s_wy[dy], wx = s_wx[xx];
            int b00 = yo + xo + lane;
            float qa = qb[b00], qbv = qb[b00+32], qc = qb[b00+1536], qd = qb[b00+1568];
            v = qa*(1.f-wy)*(1.f-wx) + qbv*(1.f-wy)*wx + qc*wy*(1.f-wx) + qd*wy*wx;
        }
        sq[lane*108 + dy*36 + xx] = v;
    }
    __syncthreads();
    float wreg[9];
    #pragma unroll
    for (int k = 0; k < 9; k++) wreg[k] = dw_w[lane*9 + k];
    float lg = offg[lane], lb = offb[lane];
    int w4 = w*4;
    float acc[4] = {0.f, 0.f, 0.f, 0.f};
    #pragma unroll
    for (int ky = 0; ky < 3; ky++) {
        const float* row = &sq[lane*108 + ky*36 + w4];
        float4 a = *(const float4*)row;
        float2 bb = *(const float2*)(row + 4);
        float e0 = a.x, e1 = a.y, e2 = a.z, e3 = a.w, e4 = bb.x, e5 = bb.y;
        float k0 = wreg[ky*3+0], k1 = wreg[ky*3+1], k2 = wreg[ky*3+2];
        acc[0] += e0*k0 + e1*k1 + e2*k2;
        acc[1] += e1*k0 + e2*k1 + e3*k2;
        acc[2] += e2*k0 + e3*k1 + e4*k2;
        acc[3] += e3*k0 + e4*k1 + e5*k2;
    }
    #pragma unroll
    for (int pp = 0; pp < 4; pp++) {
        float av = acc[pp];
        float s = av, q = av*av;
        #pragma unroll
        for (int o = 16; o; o >>= 1) { s += __shfl_xor_sync(0xffffffffu, s, o); q += __shfl_xor_sync(0xffffffffu, q, o); }
        float mu = s*(1.f/32.f);
        float var = q*(1.f/32.f) - mu*mu;
        float rs = rsqrtf(var + 1e-5f);
        float v = (av - mu)*rs*lg + lb;
        float ge = 0.5f*v*(1.f + erff(v*0.70710678118654752f));
        g_t[(size_t)bg*NPIX*32 + (oy*96 + xbase + w4 + pp)*32 + lane] = ge;
    }
}

// ---------------- k5: offset conv 3x3 (32->18) + coords (R11/R14 config) ------
// grid 768 (half-row, 48 px), 256 threads, 4 blocks/SM.
// pg = t>>4 (3 px each), half = t&1, cl = (t>>1)&7 (4 ch each); shfl-combine.
__global__ void __launch_bounds__(256, 4) k5_off(const float* __restrict__ off_b)
{
    __shared__ float st[150*40];         // 24 KB, [pos][c] pad40
    __shared__ float sw[2*9*9*32];       // 20.7 KB, [half][k][j][c]
    __shared__ int s_row[3];
    int bid = blockIdx.x;                // 768: bg*192 + oy*2 + xh
    int bg = bid / 192; int rem = bid % 192; int oy = rem >> 1; int xh = rem & 1;
    int xbase = xh*48;
    int t = threadIdx.x;                 // 256
    int wid = t >> 5, lane = t & 31;
    if (t < 3) {
        int ny = oy + t - 1;
        s_row[t] = ((unsigned)ny < 96u) ? ny*96*32 : (int)0x80000000;
    }
    __syncthreads();
    const float* src = g_t + (size_t)bg*NPIX*32;
    for (int r = wid; r < 150; r += 8) {
        int dy = (r >= 100) ? 2 : ((r >= 50) ? 1 : 0);
        int gx = xbase + (r - dy*50) - 1;
        int rb = s_row[dy];
        float v = 0.f;
        if ((rb >= 0) & ((unsigned)gx < 96u)) v = src[rb + gx*32 + lane];
        st[r*40 + lane] = v;
    }
    for (int i = t; i < 2*9*9*32; i += 256) sw[i] = g_w2[i];
    __syncthreads();

    int pg = t >> 4;                     // 0..15 (3 px each)
    int sub = t & 15;
    int half = sub & 1;
    int cl = sub >> 1;                   // 0..7 (4 channels each)
    int px0 = pg*3;                      // local x 0..45
    int c4 = cl*4;
    float acc[3][9];
    #pragma unroll
    for (int p = 0; p < 3; p++)
        #pragma unroll
        for (int j = 0; j < 9; j++) acc[p][j] = 0.f;

    #pragma unroll
    for (int k = 0; k < 9; k++) {
        int ky = k/3, kx = k%3;
        float4 tv[3];
        #pragma unroll
        for (int p = 0; p < 3; p++)
            tv[p] = *(const float4*)&st[(ky*50 + px0 + p + kx)*40 + c4];
        #pragma unroll
        for (int j = 0; j < 9; j++) {
            float4 wv = *(const float4*)&sw[((half*9 + k)*9 + j)*32 + c4];
            #pragma unroll
            for (int p = 0; p < 3; p++)
                acc[p][j] += tv[p].x*wv.x + tv[p].y*wv.y + tv[p].z*wv.z + tv[p].w*wv.w;
        }
    }
    // reduce over cl (lane bits 1..3); stays within 16-lane halves
    #pragma unroll
    for (int p = 0; p < 3; p++)
        #pragma unroll
        for (int j = 0; j < 9; j++) {
            float v = acc[p][j];
            v += __shfl_xor_sync(0xffffffffu, v, 2);
            v += __shfl_xor_sync(0xffffffffu, v, 4);
            v += __shfl_xor_sync(0xffffffffu, v, 8);
            acc[p][j] = v;
        }
    // writers: cl 0..5 -> px_w = cl>>1, j-range by cl&1
    if (cl < 6) {
        int px_w = cl >> 1;
        int jh = cl & 1;
        int ox = xbase + px0 + px_w;
        int p = oy*96 + ox;
        const float R = 47.0f/95.0f;
        int j0 = jh ? 5 : 0, j1 = jh ? 9 : 5;
        float pos = (half == 0) ? (float)oy : (float)ox;
        for (int j = j0; j < j1; j++) {
            float pred = acc[px_w][j] + off_b[j*2 + half];
            float o = tanhf(pred)*11.0f;
            float base = (half == 0) ? (float)(j/3 - 1) : (float)(j%3 - 1);
            float pix  = o + base + pos;
            g_crd[(((size_t)bg*NPIX + p)*9 + j)*2 + half] = pix * R;
        }
    }
}

// ---------------- k6: deformable attention (4 px/warp, 8 lanes/px, fp16 k,v) --
__global__ void k6_attn(const float* __restrict__ rpb, float* __restrict__ out)
{
    __shared__ float so[128*33];         // [ch][px], 16.9 KB
    int bid = blockIdx.x;                // 1152 blocks * 32 px
    int w = threadIdx.x >> 5, lane = threadIdx.x & 31;
    int sub = lane >> 3, ll = lane & 7;
    int bh = bid / 288; int b = bh >> 1, h = bh & 1;
    int prel0 = (bid % 288) * 32;
    int prel = prel0 + w*4 + sub;
    const __half* kbase = g_kh + (size_t)bh*K_SLAB;
    const __half* vbase = g_xh + (size_t)bh*XT_SLAB;
    const float* cp = g_crd + (size_t)bh*NPIX*18 + (size_t)prel*18;

    const float R = 47.0f/95.0f;
    int oy = prel / 96, ox = prel % 96;
    float ys = oy*R, xs = ox*R;
    int yq = min((int)ys, 46), xq = min((int)xs, 46);
    float wyq = ys - (float)yq, wxq = xs - (float)xq;
    const float* qb = g_q + (size_t)bh*K_SLAB;
    int q00 = (yq*48 + xq)*32 + ll*4;
    float4 qa = *(const float4*)&qb[q00];
    float4 qb2 = *(const float4*)&qb[q00+32];
    float4 qc = *(const float4*)&qb[q00+1536];
    float4 qd = *(const float4*)&qb[q00+1568];
    float a00 = (1.f-wyq)*(1.f-wxq), a01 = (1.f-wyq)*wxq, a10 = wyq*(1.f-wxq), a11 = wyq*wxq;
    const float S = 0.1767766952966369f;
    float4 qv;
    qv.x = (qa.x*a00 + qb2.x*a01 + qc.x*a10 + qd.x*a11)*S;
    qv.y = (qa.y*a00 + qb2.y*a01 + qc.y*a10 + qd.y*a11)*S;
    qv.z = (qa.z*a00 + qb2.z*a01 + qc.z*a10 + qd.z*a11)*S;
    qv.w = (qa.w*a00 + qb2.w*a01 + qc.w*a10 + qd.w*a11)*S;

    float a[9];
    __half2 hA[9], hB[9];
    int   pkA[9];
    float mx = -1e30f;
    #pragma unroll
    for (int j = 0; j < 9; j++) {
        float iy = cp[2*j], ix = cp[2*j+1];
        float y0f = floorf(iy), x0f = floorf(ix);
        float wy = iy - y0f, wx = ix - x0f;
        int y0 = (int)y0f, x0 = (int)x0f;
        pkA[j] = (y0 + 16) | ((x0 + 16) << 16);
        bool yi0 = (y0 >= 0) & (y0 < 48);
        bool yi1 = (y0 >= -1) & (y0 < 47);
        bool xi0 = (x0 >= 0) & (x0 < 48);
        bool xi1 = (x0 >= -1) & (x0 < 47);
        float w00 = (yi0 & xi0) ? (1.f-wy)*(1.f-wx) : 0.f;
        float w01 = (yi0 & xi1) ? (1.f-wy)*wx : 0.f;
        float w10 = (yi1 & xi0) ? wy*(1.f-wx) : 0.f;
        float w11 = (yi1 & xi1) ? wy*wx : 0.f;
        hA[j] = __floats2half2_rn(w00, w01);
        hB[j] = __floats2half2_rn(w10, w11);
        int yc0 = max(min(y0, 47), 0), yc1 = max(min(y0+1, 47), 0);
        int xc0 = max(min(x0, 47), 0), xc1 = max(min(x0+1, 47), 0);
        uint2 C00 = *(const uint2*)&kbase[(yc0*48+xc0)*32 + ll*4];
        uint2 C01 = *(const uint2*)&kbase[(yc0*48+xc1)*32 + ll*4];
        uint2 C10 = *(const uint2*)&kbase[(yc1*48+xc0)*32 + ll*4];
        uint2 C11 = *(const uint2*)&kbase[(yc1*48+xc1)*32 + ll*4];
        float2 c00a = __half22float2(*(__half2*)&C00.x), c00b = __half22float2(*(__half2*)&C00.y);
        float2 c01a = __half22float2(*(__half2*)&C01.x), c01b = __half22float2(*(__half2*)&C01.y);
        float2 c10a = __half22float2(*(__half2*)&C10.x), c10b = __half22float2(*(__half2*)&C10.y);
        float2 c11a = __half22float2(*(__half2*)&C11.x), c11b = __half22float2(*(__half2*)&C11.y);
        float4 rv = *(const float4*)&rpb[(h*9 + j)*32 + ll*4];
        float kx0 = c00a.x*w00 + c01a.x*w01 + c10a.x*w10 + c11a.x*w11 + rv.x;
        float kx1 = c00a.y*w00 + c01a.y*w01 + c10a.y*w10 + c11a.y*w11 + rv.y;
        float kx2 = c00b.x*w00 + c01b.x*w01 + c10b.x*w10 + c11b.x*w11 + rv.z;
        float kx3 = c00b.y*w00 + c01b.y*w01 + c10b.y*w10 + c11b.y*w11 + rv.w;
        float d = qv.x*kx0 + qv.y*kx1 + qv.z*kx2 + qv.w*kx3;
        d += __shfl_xor_sync(0xffffffffu, d, 4);
        d += __shfl_xor_sync(0xffffffffu, d, 2);
        d += __shfl_xor_sync(0xffffffffu, d, 1);
        a[j] = d;
        mx = fmaxf(mx, d);
    }
    float ssum = 0.f;
    #pragma unroll
    for (int j = 0; j < 9; j++) { a[j] = __expf(a[j] - mx); ssum += a[j]; }
    float inv = __fdividef(1.f, ssum);

    float acc[16];
    #pragma unroll
    for (int i = 0; i < 16; i++) acc[i] = 0.f;

    #pragma unroll
    for (int j = 0; j < 9; j++) {
        int y0 = (pkA[j] & 0xffff) - 16;
        int x0 = (pkA[j] >> 16) - 16;
        __half2 hAj = hA[j], hBj = hB[j];
        __half2 W00 = __half2half2(__low2half(hAj));
        __half2 W01 = __half2half2(__high2half(hAj));
        __half2 W10 = __half2half2(__low2half(hBj));
        __half2 W11 = __half2half2(__high2half(hBj));
        float aw = a[j]*inv;
        int yc0 = max(min(y0, 47), 0), yc1 = max(min(y0+1, 47), 0);
        int xc0 = max(min(x0, 47), 0), xc1 = max(min(x0+1, 47), 0);
        int r00 = (yc0*48+xc0)*128 + ll*8;
        int r01 = (yc0*48+xc1)*128 + ll*8;
        int r10 = (yc1*48+xc0)*128 + ll*8;
        int r11 = (yc1*48+xc1)*128 + ll*8;
        #pragma unroll
        for (int hb = 0; hb < 2; hb++) {
            int off = hb*64;
            float* ap = acc + hb*8;
            uint4 A00 = *(const uint4*)&vbase[r00 + off];
            uint4 A01 = *(const uint4*)&vbase[r01 + off];
            uint4 A10 = *(const uint4*)&vbase[r10 + off];
            uint4 A11 = *(const uint4*)&vbase[r11 + off];
            const __half2* h00 = (const __half2*)&A00;
            const __half2* h01 = (const __half2*)&A01;
            const __half2* h10 = (const __half2*)&A10;
            const __half2* h11 = (const __half2*)&A11;
            #pragma unroll
            for (int i = 0; i < 4; i++) {
                __half2 m = __hmul2(h00[i], W00);
                m = __hfma2(h01[i], W01, m);
                m = __hfma2(h10[i], W10, m);
                m = __hfma2(h11[i], W11, m);
                float2 f = __half22float2(m);
                ap[2*i+0] += aw*f.x;
                ap[2*i+1] += aw*f.y;
            }
        }
    }
    int pxl = w*4 + sub;
    #pragma unroll
    for (int i = 0; i < 8; i++) {
        so[(ll*8 + i)*33 + pxl]      = acc[i];
        so[(64 + ll*8 + i)*33 + pxl] = acc[8 + i];
    }
    __syncthreads();
    float* ob = out + ((size_t)(b*256 + h*128))*NPIX + prel0;
    for (int idx = threadIdx.x; idx < 4096; idx += 256) {
        int ch = idx >> 5, px = idx & 31;
        ob[(size_t)ch*NPIX + px] = so[ch*33 + px];
    }
}

extern "C" void kernel_launch(void* const* d_in, const int* in_sizes, int n_in,
                              void* d_out, int out_size)
{
    const float* x       = (const float*)d_in[0];
    const float* ln_g    = (const float*)d_in[1];
    const float* ln_b    = (const float*)d_in[2];
    const float* Wq      = (const float*)d_in[3];
    const float* Wk      = (const float*)d_in[4];
    const float* dw_w    = (const float*)d_in[5];
    const float* off_lng = (const float*)d_in[6];
    const float* off_lnb = (const float*)d_in[7];
    const float* off_w   = (const float*)d_in[8];
    const float* off_b   = (const float*)d_in[9];
    const float* rpb     = (const float*)d_in[10];

    k01_prep_tr<<<245, 256>>>(Wq, Wk, ln_g, ln_b, off_w, x);
    k2_qk<<<144, 256>>>();
    k4_dw<<<1152, 256>>>(dw_w, off_lng, off_lnb);
    k5_off<<<768, 256>>>(off_b);
    k6_attn<<<1152, 256>>>(rpb, (float*)d_out);
}